// round 1
// baseline (speedup 1.0000x reference)
#include <cuda_runtime.h>
#include <cstdint>

// Instant-NGP hash grid encode.
// B=524288 points, D=3, L=16 levels, C=2, base res H=16, growth x2,
// hashed levels use 2^19-entry tables, primes (1, 2654435761, 805459861).

static constexpr int NPTS = 524288;
static constexpr unsigned HASH_MASK = (1u << 19) - 1u;
static constexpr unsigned P1 = 2654435761u;
static constexpr unsigned P2 = 805459861u;

__global__ __launch_bounds__(256)
void hash_encode_kernel(const float* __restrict__ xin,
                        const float2* __restrict__ emb,
                        float4* __restrict__ out)
{
    const int b = blockIdx.x * 256 + threadIdx.x;  // grid sized exactly

    // map [-1,1] -> [0,1], matching reference rounding: (v + 1.0) * 0.5
    const float x = (xin[3 * b + 0] + 1.0f) * 0.5f;
    const float y = (xin[3 * b + 1] + 1.0f) * 0.5f;
    const float z = (xin[3 * b + 2] + 1.0f) * 0.5f;

    float r[32];

    unsigned off = 0;
#pragma unroll
    for (int l = 0; l < 16; ++l) {
        const int res = 16 << l;
        const float fres = (float)res;

        const float px = x * fres, py = y * fres, pz = z * fres;
        const float gx = floorf(px), gy = floorf(py), gz = floorf(pz);
        const float tx = px - gx, ty = py - gy, tz = pz - gz;
        const unsigned ix = (unsigned)gx, iy = (unsigned)gy, iz = (unsigned)gz;

        unsigned i000, i100, i010, i110, i001, i101, i011, i111;
        if (l < 3) {
            // dense level: strided index, no mod needed (idx < hsize by construction)
            const unsigned s1 = (unsigned)(res + 1);
            const unsigned s2 = s1 * s1;
            const unsigned base = ix + iy * s1 + iz * s2;
            i000 = base;            i100 = base + 1u;
            i010 = base + s1;       i110 = base + s1 + 1u;
            i001 = base + s2;       i101 = base + s2 + 1u;
            i011 = base + s1 + s2;  i111 = base + s1 + s2 + 1u;
        } else {
            // hashed level: xor of coordinate*prime, table size = 2^19
            const unsigned hx0 = ix;           const unsigned hx1 = ix + 1u;
            const unsigned hy0 = iy * P1;      const unsigned hy1 = hy0 + P1;
            const unsigned hz0 = iz * P2;      const unsigned hz1 = hz0 + P2;
            i000 = (hx0 ^ hy0 ^ hz0) & HASH_MASK;
            i100 = (hx1 ^ hy0 ^ hz0) & HASH_MASK;
            i010 = (hx0 ^ hy1 ^ hz0) & HASH_MASK;
            i110 = (hx1 ^ hy1 ^ hz0) & HASH_MASK;
            i001 = (hx0 ^ hy0 ^ hz1) & HASH_MASK;
            i101 = (hx1 ^ hy0 ^ hz1) & HASH_MASK;
            i011 = (hx0 ^ hy1 ^ hz1) & HASH_MASK;
            i111 = (hx1 ^ hy1 ^ hz1) & HASH_MASK;
        }

        const float2* __restrict__ e = emb + off;
        // 8 independent gathers -> MLP=8 per level
        const float2 v000 = __ldg(e + i000);
        const float2 v100 = __ldg(e + i100);
        const float2 v010 = __ldg(e + i010);
        const float2 v110 = __ldg(e + i110);
        const float2 v001 = __ldg(e + i001);
        const float2 v101 = __ldg(e + i101);
        const float2 v011 = __ldg(e + i011);
        const float2 v111 = __ldg(e + i111);

        const float ux = 1.0f - tx, uy = 1.0f - ty, uz = 1.0f - tz;
        const float w000 = ux * uy * uz;
        const float w100 = tx * uy * uz;
        const float w010 = ux * ty * uz;
        const float w110 = tx * ty * uz;
        const float w001 = ux * uy * tz;
        const float w101 = tx * uy * tz;
        const float w011 = ux * ty * tz;
        const float w111 = tx * ty * tz;

        float a = w000 * v000.x;
        float c = w000 * v000.y;
        a = fmaf(w100, v100.x, a);  c = fmaf(w100, v100.y, c);
        a = fmaf(w010, v010.x, a);  c = fmaf(w010, v010.y, c);
        a = fmaf(w110, v110.x, a);  c = fmaf(w110, v110.y, c);
        a = fmaf(w001, v001.x, a);  c = fmaf(w001, v001.y, c);
        a = fmaf(w101, v101.x, a);  c = fmaf(w101, v101.y, c);
        a = fmaf(w011, v011.x, a);  c = fmaf(w011, v011.y, c);
        a = fmaf(w111, v111.x, a);  c = fmaf(w111, v111.y, c);

        r[2 * l]     = a;
        r[2 * l + 1] = c;

        off += (l < 3) ? (unsigned)((res + 1) * (res + 1) * (res + 1)) : (1u << 19);
    }

    float4* __restrict__ o = out + (size_t)b * 8;
#pragma unroll
    for (int i = 0; i < 8; ++i)
        o[i] = make_float4(r[4 * i + 0], r[4 * i + 1], r[4 * i + 2], r[4 * i + 3]);
}

extern "C" void kernel_launch(void* const* d_in, const int* in_sizes, int n_in,
                              void* d_out, int out_size)
{
    // metadata order: inputs [B,3] float32, embeddings [7131219,2] float32.
    // Identify defensively by size.
    const float* xin;
    const float* emb;
    if (in_sizes[0] == NPTS * 3) {
        xin = (const float*)d_in[0];
        emb = (const float*)d_in[1];
    } else {
        xin = (const float*)d_in[1];
        emb = (const float*)d_in[0];
    }

    dim3 block(256);
    dim3 grid(NPTS / 256);  // 2048 blocks, exact
    hash_encode_kernel<<<grid, block>>>(xin, (const float2*)emb, (float4*)d_out);
}

// round 2
// speedup vs baseline: 1.1385x; 1.1385x over previous
#include <cuda_runtime.h>
#include <cstdint>

// Instant-NGP hash grid encode, round 2.
// Strategy: cut L1 wavefront count by fusing x-corner pairs into single
// aligned 16B loads wherever the pair is adjacent in the table.
//  - dense levels (0-2): pair always adjacent -> duplicated-pair float4 table.
//  - hashed levels (3-15): pair adjacent iff ix even -> realigned copy with
//    even per-level offsets so the aligned float4 covers the pair.

static constexpr int NPTS = 524288;
static constexpr unsigned HASH_MASK = (1u << 19) - 1u;
static constexpr unsigned P1 = 2654435761u;
static constexpr unsigned P2 = 805459861u;

static constexpr int DENSE_N = 4913 + 35937 + 274625;   // 315475 entries (levels 0-2)
static constexpr int HASH_LEVELS = 13;
static constexpr int HASH_F4 = HASH_LEVELS << 18;        // float4 slots (2 entries each)

// Scratch (device globals -- allocation-free).
__device__ float4 g_dense[DENSE_N];    // g_dense[i] = (emb[i], emb[i+1])
__device__ float4 g_hash4[HASH_F4];    // realigned hashed region, 16B-aligned

__global__ __launch_bounds__(256)
void prepass_kernel(const float2* __restrict__ emb)
{
    const int i = blockIdx.x * 256 + threadIdx.x;
    if (i < HASH_F4) {
        // hashed region starts at entry DENSE_N (odd) in the source
        const float2 a = __ldg(emb + DENSE_N + 2 * i);
        const float2 b = __ldg(emb + DENSE_N + 2 * i + 1);
        g_hash4[i] = make_float4(a.x, a.y, b.x, b.y);
    } else {
        const int j = i - HASH_F4;
        if (j < DENSE_N) {
            const float2 a = __ldg(emb + j);
            const float2 b = __ldg(emb + j + 1);   // j+1 <= DENSE_N: in-bounds (hashed region)
            g_dense[j] = make_float4(a.x, a.y, b.x, b.y);
        }
    }
}

__global__ __launch_bounds__(256)
void hash_encode_kernel(const float* __restrict__ xin,
                        float4* __restrict__ out)
{
    const int b = blockIdx.x * 256 + threadIdx.x;

    const float x = (xin[3 * b + 0] + 1.0f) * 0.5f;
    const float y = (xin[3 * b + 1] + 1.0f) * 0.5f;
    const float z = (xin[3 * b + 2] + 1.0f) * 0.5f;

    float r[32];

    unsigned off = 0;   // running dense offset (compile-time after unroll)
#pragma unroll
    for (int l = 0; l < 16; ++l) {
        const int res = 16 << l;
        const float fres = (float)res;

        const float px = x * fres, py = y * fres, pz = z * fres;
        const float gx = floorf(px), gy = floorf(py), gz = floorf(pz);
        const float tx = px - gx, ty = py - gy, tz = pz - gz;
        const unsigned ix = (unsigned)gx, iy = (unsigned)gy, iz = (unsigned)gz;

        float2 v000, v100, v010, v110, v001, v101, v011, v111;

        if (l < 3) {
            // dense level: x-pair always adjacent -> 4 float4 loads
            const unsigned s1 = (unsigned)(res + 1);
            const unsigned s2 = s1 * s1;
            const unsigned base = off + ix + iy * s1 + iz * s2;
            const float4 q0 = __ldg(g_dense + base);
            const float4 q1 = __ldg(g_dense + base + s1);
            const float4 q2 = __ldg(g_dense + base + s2);
            const float4 q3 = __ldg(g_dense + base + s1 + s2);
            v000 = make_float2(q0.x, q0.y);  v100 = make_float2(q0.z, q0.w);
            v010 = make_float2(q1.x, q1.y);  v110 = make_float2(q1.z, q1.w);
            v001 = make_float2(q2.x, q2.y);  v101 = make_float2(q2.z, q2.w);
            v011 = make_float2(q3.x, q3.y);  v111 = make_float2(q3.z, q3.w);
        } else {
            const unsigned lvl = (unsigned)(l - 3);
            const unsigned hy0 = iy * P1, hy1 = hy0 + P1;
            const unsigned hz0 = iz * P2, hz1 = hz0 + P2;
            const unsigned a00 = hy0 ^ hz0, a10 = hy1 ^ hz0;
            const unsigned a01 = hy0 ^ hz1, a11 = hy1 ^ hz1;

            if ((ix & 1u) == 0u) {
                // even ix: i100 = i000 ^ 1 -> pair lives in one aligned float4
                const float4* __restrict__ e4 = g_hash4 + (lvl << 18);
                const unsigned m0 = (ix ^ a00) & HASH_MASK;
                const unsigned m1 = (ix ^ a10) & HASH_MASK;
                const unsigned m2 = (ix ^ a01) & HASH_MASK;
                const unsigned m3 = (ix ^ a11) & HASH_MASK;
                const float4 q0 = __ldg(e4 + (m0 >> 1));
                const float4 q1 = __ldg(e4 + (m1 >> 1));
                const float4 q2 = __ldg(e4 + (m2 >> 1));
                const float4 q3 = __ldg(e4 + (m3 >> 1));
                // m even -> v(x=0) is the low half; m odd -> swapped
                v000 = (m0 & 1u) ? make_float2(q0.z, q0.w) : make_float2(q0.x, q0.y);
                v100 = (m0 & 1u) ? make_float2(q0.x, q0.y) : make_float2(q0.z, q0.w);
                v010 = (m1 & 1u) ? make_float2(q1.z, q1.w) : make_float2(q1.x, q1.y);
                v110 = (m1 & 1u) ? make_float2(q1.x, q1.y) : make_float2(q1.z, q1.w);
                v001 = (m2 & 1u) ? make_float2(q2.z, q2.w) : make_float2(q2.x, q2.y);
                v101 = (m2 & 1u) ? make_float2(q2.x, q2.y) : make_float2(q2.z, q2.w);
                v011 = (m3 & 1u) ? make_float2(q3.z, q3.w) : make_float2(q3.x, q3.y);
                v111 = (m3 & 1u) ? make_float2(q3.x, q3.y) : make_float2(q3.z, q3.w);
            } else {
                // odd ix: corners not adjacent -> 8 scalar float2 gathers
                const float2* __restrict__ e =
                    reinterpret_cast<const float2*>(g_hash4) + (lvl << 19);
                const unsigned ixp = ix + 1u;
                v000 = __ldg(e + ((ix  ^ a00) & HASH_MASK));
                v100 = __ldg(e + ((ixp ^ a00) & HASH_MASK));
                v010 = __ldg(e + ((ix  ^ a10) & HASH_MASK));
                v110 = __ldg(e + ((ixp ^ a10) & HASH_MASK));
                v001 = __ldg(e + ((ix  ^ a01) & HASH_MASK));
                v101 = __ldg(e + ((ixp ^ a01) & HASH_MASK));
                v011 = __ldg(e + ((ix  ^ a11) & HASH_MASK));
                v111 = __ldg(e + ((ixp ^ a11) & HASH_MASK));
            }
        }

        const float ux = 1.0f - tx, uy = 1.0f - ty, uz = 1.0f - tz;
        const float w000 = ux * uy * uz;
        const float w100 = tx * uy * uz;
        const float w010 = ux * ty * uz;
        const float w110 = tx * ty * uz;
        const float w001 = ux * uy * tz;
        const float w101 = tx * uy * tz;
        const float w011 = ux * ty * tz;
        const float w111 = tx * ty * tz;

        float a = w000 * v000.x;
        float c = w000 * v000.y;
        a = fmaf(w100, v100.x, a);  c = fmaf(w100, v100.y, c);
        a = fmaf(w010, v010.x, a);  c = fmaf(w010, v010.y, c);
        a = fmaf(w110, v110.x, a);  c = fmaf(w110, v110.y, c);
        a = fmaf(w001, v001.x, a);  c = fmaf(w001, v001.y, c);
        a = fmaf(w101, v101.x, a);  c = fmaf(w101, v101.y, c);
        a = fmaf(w011, v011.x, a);  c = fmaf(w011, v011.y, c);
        a = fmaf(w111, v111.x, a);  c = fmaf(w111, v111.y, c);

        r[2 * l]     = a;
        r[2 * l + 1] = c;

        off += (l < 3) ? (unsigned)((res + 1) * (res + 1) * (res + 1)) : 0u;
    }

    float4* __restrict__ o = out + (size_t)b * 8;
#pragma unroll
    for (int i = 0; i < 8; ++i)
        o[i] = make_float4(r[4 * i + 0], r[4 * i + 1], r[4 * i + 2], r[4 * i + 3]);
}

extern "C" void kernel_launch(void* const* d_in, const int* in_sizes, int n_in,
                              void* d_out, int out_size)
{
    const float* xin;
    const float* emb;
    if (in_sizes[0] == NPTS * 3) {
        xin = (const float*)d_in[0];
        emb = (const float*)d_in[1];
    } else {
        xin = (const float*)d_in[1];
        emb = (const float*)d_in[0];
    }

    // prepass: realign + dup tables (runs every replay; streaming, ~18us)
    const int prep_total = HASH_F4 + DENSE_N;
    prepass_kernel<<<(prep_total + 255) / 256, 256>>>((const float2*)emb);

    hash_encode_kernel<<<NPTS / 256, 256>>>(xin, (float4*)d_out);
}

// round 3
// speedup vs baseline: 1.2249x; 1.0758x over previous
#include <cuda_runtime.h>
#include <cuda_fp16.h>
#include <cstdint>

// Instant-NGP hash grid encode, round 3.
// fp16 tables: 16B load covers 4 consecutive entries -> x-corner pair fused
// into one load whenever mask = ix^(ix+1) < 4 (75% of cases).
// Dense levels: fp16 duplicated-pair table (8B loads).
// Output: warp-local smem transpose -> coalesced STG.

static constexpr int NPTS = 524288;
static constexpr unsigned HASH_MASK = (1u << 19) - 1u;
static constexpr unsigned P1 = 2654435761u;
static constexpr unsigned P2 = 805459861u;

static constexpr int DENSE_N = 4913 + 35937 + 274625;   // 315475 entries, levels 0-2
static constexpr int NH = 13 << 19;                      // hashed entries (13 levels x 2^19)

// fp16 tables (device globals; allocation-free)
__device__ __align__(16) uint32_t g_hash_h[NH];   // half2 per entry, 26MB, level-major
__device__ uint2 g_dense_h[DENSE_N];              // {e[i], e[i+1]} as 4 halves, 2.5MB

__device__ __forceinline__ uint32_t pack_h2(float2 v) {
    __half2 h = __float22half2_rn(v);
    return *reinterpret_cast<uint32_t*>(&h);
}
__device__ __forceinline__ float2 unpack_h2(uint32_t u) {
    __half2 h = *reinterpret_cast<__half2*>(&u);
    return __half22float2(h);
}
// select entry i (0..3) from a 16B slot of 4 half2 entries
__device__ __forceinline__ float2 pick4(uint4 q, unsigned i) {
    const uint32_t lo = (i & 2u) ? q.z : q.x;
    const uint32_t hi = (i & 2u) ? q.w : q.y;
    return unpack_h2((i & 1u) ? hi : lo);
}

__global__ __launch_bounds__(256)
void prepass_kernel(const float2* __restrict__ emb)
{
    const int i = blockIdx.x * 256 + threadIdx.x;
    if (i < NH) {
        g_hash_h[i] = pack_h2(__ldg(emb + DENSE_N + i));
    } else {
        const int j = i - NH;
        if (j < DENSE_N) {
            const float2 a = __ldg(emb + j);
            const float2 b = __ldg(emb + j + 1);   // j+1 <= DENSE_N: still in-bounds
            g_dense_h[j] = make_uint2(pack_h2(a), pack_h2(b));
        }
    }
}

__global__ __launch_bounds__(256)
void hash_encode_kernel(const float* __restrict__ xin,
                        float4* __restrict__ out)
{
    __shared__ float4 sm[256][8];   // 32KB; warp-local transpose buffer

    const unsigned tid  = threadIdx.x;
    const unsigned lane = tid & 31u;
    const int b = blockIdx.x * 256 + tid;

    const float x = (xin[3 * b + 0] + 1.0f) * 0.5f;
    const float y = (xin[3 * b + 1] + 1.0f) * 0.5f;
    const float z = (xin[3 * b + 2] + 1.0f) * 0.5f;

    unsigned off = 0;   // dense level base (compile-time after unroll)
#pragma unroll
    for (int l = 0; l < 16; ++l) {
        const int res = 16 << l;
        const float fres = (float)res;

        const float px = x * fres, py = y * fres, pz = z * fres;
        const float gx = floorf(px), gy = floorf(py), gz = floorf(pz);
        const float tx = px - gx, ty = py - gy, tz = pz - gz;
        const unsigned ix = (unsigned)gx, iy = (unsigned)gy, iz = (unsigned)gz;

        float2 v000, v100, v010, v110, v001, v101, v011, v111;

        if (l < 3) {
            // dense: dup-pair table, pair always fused into one 8B load
            const unsigned s1 = (unsigned)(res + 1);
            const unsigned s2 = s1 * s1;
            const unsigned base = off + ix + iy * s1 + iz * s2;
            const uint2 p0 = __ldg(g_dense_h + base);
            const uint2 p1 = __ldg(g_dense_h + base + s1);
            const uint2 p2 = __ldg(g_dense_h + base + s2);
            const uint2 p3 = __ldg(g_dense_h + base + s1 + s2);
            v000 = unpack_h2(p0.x);  v100 = unpack_h2(p0.y);
            v010 = unpack_h2(p1.x);  v110 = unpack_h2(p1.y);
            v001 = unpack_h2(p2.x);  v101 = unpack_h2(p2.y);
            v011 = unpack_h2(p3.x);  v111 = unpack_h2(p3.y);
        } else {
            const unsigned lvl = (unsigned)(l - 3);
            const uint4* __restrict__ tab =
                reinterpret_cast<const uint4*>(g_hash_h) + ((size_t)lvl << 17);

            const unsigned hy0 = iy * P1, hy1 = hy0 + P1;
            const unsigned hz0 = iz * P2, hz1 = hz0 + P2;
            const unsigned a00 = hy0 ^ hz0, a10 = hy1 ^ hz0;
            const unsigned a01 = hy0 ^ hz1, a11 = hy1 ^ hz1;

            const unsigned mask = ix ^ (ix + 1u);   // 2^(t+1)-1
            const unsigned m00 = (ix ^ a00) & HASH_MASK;
            const unsigned m10 = (ix ^ a10) & HASH_MASK;
            const unsigned m01 = (ix ^ a01) & HASH_MASK;
            const unsigned m11 = (ix ^ a11) & HASH_MASK;
            const unsigned n00 = (m00 ^ mask) & HASH_MASK;  // partner (ix+1)
            const unsigned n10 = (m10 ^ mask) & HASH_MASK;
            const unsigned n01 = (m01 ^ mask) & HASH_MASK;
            const unsigned n11 = (m11 ^ mask) & HASH_MASK;

            uint4 qa = __ldg(tab + (m00 >> 2));
            uint4 qb = __ldg(tab + (m10 >> 2));
            uint4 qc = __ldg(tab + (m01 >> 2));
            uint4 qd = __ldg(tab + (m11 >> 2));
            uint4 ra = qa, rb = qb, rc = qc, rd = qd;
            if (mask >= 4u) {   // partner lives in a different 16B slot (25%)
                ra = __ldg(tab + (n00 >> 2));
                rb = __ldg(tab + (n10 >> 2));
                rc = __ldg(tab + (n01 >> 2));
                rd = __ldg(tab + (n11 >> 2));
            }
            v000 = pick4(qa, m00 & 3u);  v100 = pick4(ra, n00 & 3u);
            v010 = pick4(qb, m10 & 3u);  v110 = pick4(rb, n10 & 3u);
            v001 = pick4(qc, m01 & 3u);  v101 = pick4(rc, n01 & 3u);
            v011 = pick4(qd, m11 & 3u);  v111 = pick4(rd, n11 & 3u);
        }

        const float ux = 1.0f - tx, uy = 1.0f - ty, uz = 1.0f - tz;
        const float w000 = ux * uy * uz;
        const float w100 = tx * uy * uz;
        const float w010 = ux * ty * uz;
        const float w110 = tx * ty * uz;
        const float w001 = ux * uy * tz;
        const float w101 = tx * uy * tz;
        const float w011 = ux * ty * tz;
        const float w111 = tx * ty * tz;

        float a = w000 * v000.x;
        float c = w000 * v000.y;
        a = fmaf(w100, v100.x, a);  c = fmaf(w100, v100.y, c);
        a = fmaf(w010, v010.x, a);  c = fmaf(w010, v010.y, c);
        a = fmaf(w110, v110.x, a);  c = fmaf(w110, v110.y, c);
        a = fmaf(w001, v001.x, a);  c = fmaf(w001, v001.y, c);
        a = fmaf(w101, v101.x, a);  c = fmaf(w101, v101.y, c);
        a = fmaf(w011, v011.x, a);  c = fmaf(w011, v011.y, c);
        a = fmaf(w111, v111.x, a);  c = fmaf(w111, v111.y, c);

        // stash into smem with xor swizzle (float4-granular) for conflict-free phases
        float2* cell = reinterpret_cast<float2*>(
            &sm[tid][(unsigned)(l >> 1) ^ (lane & 7u)]) + (l & 1);
        *cell = make_float2(a, c);

        off += (l < 3) ? (unsigned)((res + 1) * (res + 1) * (res + 1)) : 0u;
    }

    __syncwarp();

    // coalesced store: each warp writes its own 4KB contiguous output region
    const unsigned w = tid >> 5;
    float4* __restrict__ of4 = out + ((size_t)blockIdx.x * 256 + w * 32) * 8;
#pragma unroll
    for (int j = 0; j < 8; ++j) {
        const unsigned g  = (unsigned)j * 32u + lane;
        const unsigned p  = g >> 3;        // warp-local point row
        const unsigned c4 = g & 7u;        // float4 column
        of4[g] = sm[w * 32 + p][c4 ^ (p & 7u)];
    }
}

extern "C" void kernel_launch(void* const* d_in, const int* in_sizes, int n_in,
                              void* d_out, int out_size)
{
    const float* xin;
    const float* emb;
    if (in_sizes[0] == NPTS * 3) {
        xin = (const float*)d_in[0];
        emb = (const float*)d_in[1];
    } else {
        xin = (const float*)d_in[1];
        emb = (const float*)d_in[0];
    }

    const int prep_total = NH + DENSE_N;
    prepass_kernel<<<(prep_total + 255) / 256, 256>>>((const float2*)emb);

    hash_encode_kernel<<<NPTS / 256, 256>>>(xin, (float4*)d_out);
}